// round 16
// baseline (speedup 1.0000x reference)
#include <cuda_runtime.h>

// QNN_72988674228630: 10-qubit, 2-layer RY+CNOT circuit, 8192 circuits.
//
// Bond-2 MPS transfer-matrix contraction, ONE thread per circuit (~220 ops).
// Device time sits at the single-launch floor (~4.7 us); across R12-R15 the
// executed-instruction count varied 60x with device time invariant, so the
// only remaining lever is launch-side. R16: smallest grid so far — 64 CTAs
// x 128 threads (one CTA per SM on 64 SMs, 1 warp per SMSP, zero contention),
// halving CTA dispatch count vs the best measured config (128x64, 4.70us).
//
// Derivation (bit p = 9 - qubit q; CNOT chain P = GF(2) suffix-XOR M):
//   psi = P R2 P R1 |0>,  out = sum_p <psi| Z_p |psi>
//   P^T Z_p P = Z_p Z_{p+1} ... Z_9             (suffix Z-string)
//   R2^T Z_m R2 = cos(t2) Z_m - sin(t2) X_m     (per site, FULL angle)
//   chi_j = prod_b f_b(j_b ^ j_{b+1})           (bond-2 MPS, f = (cos,sin) of t1/2)
// Contraction: symmetric 2x2 environment S swept p=9..0, M = F_p S F_p
// (F_p = [[c,s],[s,c]]), S <- (ga,-sg,-ga).M.  Left environment == (1,1)
// identically (c^2+s^2=1 induction), so E_{p+1} = trace(M); E_0 = full sum
// of the final S with the off-diagonal twice.

__global__ __launch_bounds__(128, 1)
void qnn_kernel(const float* __restrict__ x,      // [128, 10]
                const float* __restrict__ w,      // [64, 10, 2]
                float* __restrict__ out)          // [64, 128] flat
{
    const int t  = blockIdx.x * 128 + threadIdx.x;  // 0..8191, one circuit
    const int of = t >> 7;          // out_feature (warp-uniform -> broadcast)
    const int nb = t & 127;         // batch row (coalesced across lanes)

    // --- Loads first (both streams in flight), then angle prep.
    //     Bit p <-> qubit q = 9-p.  t1h[p] = (x_q + w_q0)/2 ; t2a[p] = w_q1.
    float t1h[10], t2a[10];
    {
        const float2* xp = (const float2*)(x + nb * 10);   // 8B-aligned rows
        const float4* wp = (const float4*)(w + of * 20);   // 16B-aligned rows
        float2 xr[5]; float4 wr[5];
#pragma unroll
        for (int i = 0; i < 5; i++) xr[i] = xp[i];
#pragma unroll
        for (int i = 0; i < 5; i++) wr[i] = wp[i];
        float xv[10], wv[20];
#pragma unroll
        for (int i = 0; i < 5; i++) {
            xv[2*i] = xr[i].x; xv[2*i+1] = xr[i].y;
            wv[4*i] = wr[i].x; wv[4*i+1] = wr[i].y;
            wv[4*i+2] = wr[i].z; wv[4*i+3] = wr[i].w;
        }
#pragma unroll
        for (int q = 0; q < 10; q++) {
            t1h[9 - q] = 0.5f * (xv[q] + wv[2*q]);
            t2a[9 - q] = wv[2*q + 1];
        }
    }

    // --- MPS site factors f_p = (cos, sin) of the half layer-1 angle.
    float fc[10], fs[10];
#pragma unroll
    for (int p = 0; p < 10; p++)
        __sincosf(t1h[p], &fs[p], &fc[p]);

    // --- Top boundary (p = 9): S = (ga,-sg,-ga) . outer(f9, f9).
    float s00, s01, s11;
    {
        float gav, sgv; __sincosf(t2a[9], &sgv, &gav);
        const float c = fc[9], s = fs[9];
        s00 =  gav * (c * c);
        s01 = -sgv * (c * s);
        s11 = -gav * (s * s);
    }

    // --- Sweep p = 8..0: M = F_p S F_p; accumulate trace(M); S = g_p . M.
    float acc0 = 0.0f, acc1 = 0.0f;
#pragma unroll
    for (int p = 8; p >= 0; p--) {
        const float c = fc[p], s = fs[p];
        float gav, sgv; __sincosf(t2a[p], &sgv, &gav);   // hidden under FMAs
        const float t0  = fmaf(c, s00, s * s01);
        const float t1v = fmaf(c, s01, s * s11);
        const float t2v = fmaf(s, s00, c * s01);
        const float t3v = fmaf(s, s01, c * s11);
        const float M00 = fmaf(c, t0,  s * t1v);
        const float M01 = fmaf(s, t0,  c * t1v);
        const float M11 = fmaf(s, t2v, c * t3v);
        acc0 += M00;                 // E_{p+1} = trace(M); two parallel chains
        acc1 += M11;
        s00 =  gav * M00;
        s01 = -sgv * M01;
        s11 = -gav * M11;
    }

    // --- E_0 folded into the accumulator tree; 2*s01 via one FMA.
    out[t] = fmaf(2.0f, s01, (acc0 + s00) + (acc1 + s11));
}

extern "C" void kernel_launch(void* const* d_in, const int* in_sizes, int n_in,
                              void* d_out, int out_size)
{
    const float* x = (const float*)d_in[0];   // (128, 10) fp32
    const float* w = (const float*)d_in[1];   // (64, 10, 2) fp32
    float* out = (float*)d_out;               // 8192 fp32

    // One thread per circuit; 64 CTAs x 128 threads (1 warp/SMSP on 64 SMs).
    qnn_kernel<<<64, 128>>>(x, w, out);
}

// round 17
// speedup vs baseline: 1.1088x; 1.1088x over previous
#include <cuda_runtime.h>

// QNN_72988674228630: 10-qubit, 2-layer RY+CNOT circuit, 8192 circuits.
//
// R17: REPRODUCIBILITY PIN — byte-for-byte resubmission of the R13 kernel,
// the best-measured configuration of the session (wall 5.79us, device 4.80).
// R12-R16 established that device time is invariant (~4.7-5.3us) across a 60x
// span of executed instructions and all grid shapes: the kernel runs at the
// single-launch floor (dispatch + ramp + warp lifetime), and the remaining
// wall spread (5.8-6.9us) is replay-path noise. This round tests whether
// R13's 5.79 replicates; either way this configuration is the final kernel.
//
// Algorithm: bond-dimension-2 MPS transfer-matrix contraction, ONE thread per
// circuit (~330 scalar ops vs 2*1024-amp state-vector simulation).
// Derivation (bit p = 9 - qubit q; CNOT chain P = GF(2) suffix-XOR M):
//   psi = P R2 P R1 |0>,  out = sum_p <psi| Z_p |psi>
//   P^T Z_p P = Z_p Z_{p+1} ... Z_9             (suffix Z-string)
//   R2^T Z_m R2 = cos(t2) Z_m - sin(t2) X_m     (per site, FULL angle)
//   chi_j = prod_b f_b(j_b ^ j_{b+1})           (bond-2 MPS, f = (cos,sin) of t1/2)
// Contraction: symmetric 2x2 environment S swept p=9..0 with M = F_p S F_p
// (F_p = [[c,s],[s,c]]), then S <- (ga,-sg,-ga) . M; left diagonal
// environment d_p built p=0..8 (identically (1,1), kept as in R13 for exact
// reproduction); E_{p+1} = d_p . diag(M); E_0 = full sum of S_0.

__global__ __launch_bounds__(32, 1)
void qnn_kernel(const float* __restrict__ x,      // [128, 10]
                const float* __restrict__ w,      // [64, 10, 2]
                float* __restrict__ out)          // [64, 128] flat
{
    const int t  = blockIdx.x * 32 + threadIdx.x;   // 0..8191, one circuit
    const int of = t >> 7;          // out_feature (warp-uniform -> broadcast loads)
    const int nb = t & 127;         // batch row (consecutive across lanes)

    // --- Loads: x row = 5 x float2 (8B aligned), w row = 5 x float4 (uniform).
    float xv[10], wv[20];
    {
        const float2* xp = (const float2*)(x + nb * 10);
#pragma unroll
        for (int i = 0; i < 5; i++) {
            const float2 v = xp[i];
            xv[2*i] = v.x; xv[2*i+1] = v.y;
        }
        const float4* wp = (const float4*)(w + of * 20);
#pragma unroll
        for (int i = 0; i < 5; i++) {
            const float4 v = wp[i];
            wv[4*i] = v.x; wv[4*i+1] = v.y; wv[4*i+2] = v.z; wv[4*i+3] = v.w;
        }
    }

    // --- Per-bit angle data. Bit p <-> qubit q = 9-p.
    float fc[10], fs[10], ga[10], sg[10];
#pragma unroll
    for (int q = 0; q < 10; q++) {
        const int p = 9 - q;
        __sincosf(0.5f * (xv[q] + wv[2*q]), &fs[p], &fc[p]);
        __sincosf(wv[2*q + 1],              &sg[p], &ga[p]);
    }

    // --- Left diagonal environments d_p (p = 0..8), bottom-up.
    float d0[9], d1[9];
    d0[0] = 1.0f; d1[0] = 1.0f;
#pragma unroll
    for (int p = 0; p < 8; p++) {
        const float a = fc[p] * fc[p];
        const float b = fs[p] * fs[p];
        d0[p+1] = fmaf(d0[p], a, d1[p] * b);
        d1[p+1] = fmaf(d0[p], b, d1[p] * a);
    }

    // --- Top boundary (p = 9): S = (ga,-sg,-ga) . outer(f9, f9).
    float s00, s01, s11;
    {
        const float c = fc[9], s = fs[9];
        s00 =  ga[9] * (c * c);
        s01 = -sg[9] * (c * s);
        s11 = -ga[9] * (s * s);
    }

    // --- Sweep p = 8..0. Two accumulator chains to shorten the tail.
    float acc0 = 0.0f, acc1 = 0.0f;
#pragma unroll
    for (int p = 8; p >= 0; p--) {
        const float c = fc[p], s = fs[p];
        const float t0  = fmaf(c, s00, s * s01);
        const float t1v = fmaf(c, s01, s * s11);
        const float t2v = fmaf(s, s00, c * s01);
        const float t3v = fmaf(s, s01, c * s11);
        const float M00 = fmaf(c, t0,  s * t1v);
        const float M01 = fmaf(s, t0,  c * t1v);
        const float M11 = fmaf(s, t2v, c * t3v);
        if (p & 1) acc1 = fmaf(d0[p], M00, fmaf(d1[p], M11, acc1));
        else       acc0 = fmaf(d0[p], M00, fmaf(d1[p], M11, acc0));
        s00 =  ga[p] * M00;
        s01 = -sg[p] * M01;
        s11 = -ga[p] * M11;
    }

    // --- E_0 = full contraction of S_0 (off-diagonal twice).
    out[t] = acc0 + acc1 + s00 + 2.0f * s01 + s11;
}

extern "C" void kernel_launch(void* const* d_in, const int* in_sizes, int n_in,
                              void* d_out, int out_size)
{
    const float* x = (const float*)d_in[0];   // (128, 10) fp32
    const float* w = (const float*)d_in[1];   // (64, 10, 2) fp32
    float* out = (float*)d_out;               // 8192 fp32

    // One thread per circuit; 256 blocks x 32 threads covers all 148 SMs.
    qnn_kernel<<<256, 32>>>(x, w, out);
}